// round 4
// baseline (speedup 1.0000x reference)
#include <cuda_runtime.h>
#include <cuda_bf16.h>
#include <cstdint>

// ---------------- problem dims ----------------
constexpr int kB  = 4;
constexpr int kL  = 4096;
constexpr int kD  = 1024;
constexpr int kDI = 2048;
constexpr int kM  = kB * kL;          // 16384 rows
constexpr int kDS = 16;
constexpr int kDC = 4;
constexpr int kKS = 9;                // K_SYM

// ---------------- scratch (static device memory; allocation APIs are banned) ----
__device__ __nv_bfloat16 g_hn  [(size_t)kM * kD];
__device__ __nv_bfloat16 g_gate[(size_t)kM * kDI];
__device__ __nv_bfloat16 g_val [(size_t)kM * kDI];
__device__ __nv_bfloat16 g_a1  [(size_t)kM * kDI];
__device__ float         g_a2  [(size_t)kM * kDS];
__device__ float         g_C1  [(size_t)kDS * (kDI/2)];
__device__ __nv_bfloat16 g_b1  [(size_t)kM * kDI];
__device__ __nv_bfloat16 g_b2  [(size_t)kM * kDI];
__device__ __nv_bfloat16 g_y   [(size_t)kM * kDI];
__device__ __nv_bfloat16 g_y2  [(size_t)kM * kDI];
__device__ __nv_bfloat16 g_w_in  [(size_t)2*kDI * kD];
__device__ __nv_bfloat16 g_w_pw  [(size_t)kDI * kDI];
__device__ __nv_bfloat16 g_w_hb  [(size_t)(kDI/2) * kDI];
__device__ __nv_bfloat16 g_w_fuse[(size_t)kDI * kDI];
__device__ __nv_bfloat16 g_w_out [(size_t)kD * kDI];

#define DEVFN __device__ __forceinline__

// ---------------- small helpers ----------------
DEVFN void cp_async16(void* smem, const void* gmem) {
    uint32_t a = (uint32_t)__cvta_generic_to_shared(smem);
    asm volatile("cp.async.cg.shared.global [%0], [%1], 16;\n" :: "r"(a), "l"(gmem));
}
DEVFN void cp_commit()   { asm volatile("cp.async.commit_group;\n"); }
DEVFN void cp_wait_all() { asm volatile("cp.async.wait_group 0;\n"); }

// ---------------- generic fp32 -> bf16 ----------------
__global__ void f2bf_kernel(const float* __restrict__ src, __nv_bfloat16* __restrict__ dst, int n) {
    int i = blockIdx.x * blockDim.x + threadIdx.x;
    int stride = gridDim.x * blockDim.x;
    for (; i < n; i += stride) dst[i] = __float2bfloat16(src[i]);
}

// ---------------- rmsnorm: fp32 in -> bf16 out ----------------
__global__ void rmsnorm_kernel(const float* __restrict__ x, const float* __restrict__ w,
                               __nv_bfloat16* __restrict__ out) {
    int m = blockIdx.x;
    const float* xr = x + (size_t)m * kD;
    float ss = 0.f;
    for (int c = threadIdx.x; c < kD; c += 256) { float v = xr[c]; ss += v * v; }
    #pragma unroll
    for (int o = 16; o; o >>= 1) ss += __shfl_xor_sync(0xffffffffu, ss, o);
    __shared__ float red[8];
    if ((threadIdx.x & 31) == 0) red[threadIdx.x >> 5] = ss;
    __syncthreads();
    float tot = 0.f;
    #pragma unroll
    for (int i = 0; i < 8; ++i) tot += red[i];
    float scale = rsqrtf(tot * (1.f / kD) + 1e-6f);
    for (int c = threadIdx.x; c < kD; c += 256)
        out[(size_t)m * kD + c] = __float2bfloat16(w[c] * xr[c] * scale);
}

// ---------------- depthwise conv, kernel 4, pad (1,2) ----------------
__global__ void dwconv4_kernel(const __nv_bfloat16* __restrict__ val,
                               const float* __restrict__ kw, const float* __restrict__ kb,
                               __nv_bfloat16* __restrict__ out) {
    int idx = blockIdx.x * blockDim.x + threadIdx.x;   // < kM*kDI
    int c = idx & (kDI - 1);
    int m = idx >> 11;
    int l = m & (kL - 1);
    float acc = kb[c];
    #pragma unroll
    for (int t = 0; t < kDC; ++t) {
        int ll = l + t - 1;
        if (ll >= 0 && ll < kL)
            acc += __bfloat162float(val[(size_t)(m + t - 1) * kDI + c]) * kw[c * kDC + t];
    }
    out[idx] = __float2bfloat16(acc);
}

// ---------------- depthwise conv, kernel 9, pad (4,4), + SiLU ----------------
__global__ void dwconv9_silu_kernel(const __nv_bfloat16* __restrict__ val,
                                    const float* __restrict__ kw, const float* __restrict__ kb,
                                    __nv_bfloat16* __restrict__ out) {
    int idx = blockIdx.x * blockDim.x + threadIdx.x;
    int c = idx & (kDI - 1);
    int m = idx >> 11;
    int l = m & (kL - 1);
    float acc = kb[c];
    #pragma unroll
    for (int t = 0; t < kKS; ++t) {
        int ll = l + t - 4;
        if (ll >= 0 && ll < kL)
            acc += __bfloat162float(val[(size_t)(m + t - 4) * kDI + c]) * kw[c * kKS + t];
    }
    float s = acc / (1.f + __expf(-acc));   // silu
    out[idx] = __float2bfloat16(s);
}

// ---------------- a2 = a1 @ A  (K=2048, N=16); one warp per row ----------------
__global__ void lowrank_a2_kernel(const __nv_bfloat16* __restrict__ a1,
                                  const float* __restrict__ Amat,
                                  float* __restrict__ a2) {
    int warp = (blockIdx.x * blockDim.x + threadIdx.x) >> 5;
    int lane = threadIdx.x & 31;
    if (warp >= kM) return;
    float acc[kDS];
    #pragma unroll
    for (int s = 0; s < kDS; ++s) acc[s] = 0.f;
    const __nv_bfloat16* row = a1 + (size_t)warp * kDI;
    for (int c = lane; c < kDI; c += 32) {
        float av = __bfloat162float(row[c]);
        const float* Ac = Amat + (size_t)c * kDS;
        #pragma unroll
        for (int s = 0; s < kDS; ++s) acc[s] += av * Ac[s];
    }
    #pragma unroll
    for (int s = 0; s < kDS; ++s) {
        #pragma unroll
        for (int o = 16; o; o >>= 1) acc[s] += __shfl_xor_sync(0xffffffffu, acc[s], o);
    }
    if (lane == 0) {
        #pragma unroll
        for (int s = 0; s < kDS; ++s) a2[(size_t)warp * kDS + s] = acc[s];
    }
}

// ---------------- C1[s,h] = sum_d Bm[s,d] * ha_w[h,d] ; one warp per (s,h) -----
__global__ void c1_kernel(const float* __restrict__ Bm, const float* __restrict__ ha_w,
                          float* __restrict__ C1) {
    int g = (blockIdx.x * blockDim.x + threadIdx.x) >> 5;
    int lane = threadIdx.x & 31;
    if (g >= kDS * (kDI/2)) return;
    int s = g >> 10;              // /1024
    int h = g & 1023;
    float acc = 0.f;
    const float* br = Bm + (size_t)s * kDI;
    const float* hr = ha_w + (size_t)h * kDI;
    for (int d = lane; d < kDI; d += 32) acc += br[d] * hr[d];
    #pragma unroll
    for (int o = 16; o; o >>= 1) acc += __shfl_xor_sync(0xffffffffu, acc, o);
    if (lane == 0) C1[(size_t)s * 1024 + h] = acc;
}

// ---------------- y[:, :1024] = a2 @ C1 + ha_b  (K=16) -------------------------
__global__ void a4_kernel(const float* __restrict__ a2, const float* __restrict__ C1,
                          const float* __restrict__ ha_b, __nv_bfloat16* __restrict__ y) {
    int idx = blockIdx.x * blockDim.x + threadIdx.x;   // < kM*1024
    int h = idx & 1023;
    int m = idx >> 10;
    float acc = ha_b[h];
    const float* ar = a2 + (size_t)m * kDS;
    #pragma unroll
    for (int s = 0; s < kDS; ++s) acc += ar[s] * C1[(size_t)s * 1024 + h];
    y[(size_t)m * kDI + h] = __float2bfloat16(acc);
}

// ==================== bf16 tensor-core GEMM ====================
// C[M,N] = A[M,K] @ B[N,K]^T + bias,  tiles 128x128x32, 8 warps (2x4), warp 64x32
// MODE 0: store bf16 at out[m*ldc + coff + n]
// MODE 1: n<2048 -> sigmoid -> gate ; n>=2048 -> raw -> val   (ldc fixed 2048)
// MODE 2: store bf16 (acc+bias)*gate[m*2048+n]
// MODE 3: outF[m*ldc+n] = resid[m*ldc+n] + acc + bias
constexpr int BM = 128, BN = 128, BK = 32, LDS = BK + 8;   // pad 8 elems (16B-aligned rows)

template<int MODE>
__global__ __launch_bounds__(256, 2)
void gemm_bf16(const __nv_bfloat16* __restrict__ Ag,
               const __nv_bfloat16* __restrict__ Bg,
               const float* __restrict__ bias,
               int K, int N,
               __nv_bfloat16* __restrict__ outB,
               __nv_bfloat16* __restrict__ out1,
               const __nv_bfloat16* __restrict__ gate,
               const float* __restrict__ resid,
               float* __restrict__ outF,
               int ldc, int coff) {
    __shared__ __align__(16) __nv_bfloat16 As[2][BM * LDS];
    __shared__ __align__(16) __nv_bfloat16 Bs[2][BN * LDS];
    const int tid  = threadIdx.x;
    const int lane = tid & 31;
    const int warp = tid >> 5;
    const int wm = warp >> 2, wn = warp & 3;
    const int mBase = blockIdx.y * BM;
    const int nBase = blockIdx.x * BN;

    float c[4][4][4];
    #pragma unroll
    for (int i = 0; i < 4; ++i)
        #pragma unroll
        for (int j = 0; j < 4; ++j)
            #pragma unroll
            for (int q = 0; q < 4; ++q) c[i][j][q] = 0.f;

    const int KT = K / BK;

    auto load_tile = [&](int kt, int st) {
        int k0 = kt * BK;
        #pragma unroll
        for (int i = 0; i < 2; ++i) {
            int lin = tid + i * 256;          // 0..511
            int r   = lin >> 2;
            int cc  = (lin & 3) << 3;
            cp_async16(&As[st][r * LDS + cc], Ag + (size_t)(mBase + r) * K + k0 + cc);
            cp_async16(&Bs[st][r * LDS + cc], Bg + (size_t)(nBase + r) * K + k0 + cc);
        }
    };

    load_tile(0, 0); cp_commit();
    int st = 0;
    for (int kt = 0; kt < KT; ++kt) {
        cp_wait_all();
        __syncthreads();
        if (kt + 1 < KT) { load_tile(kt + 1, st ^ 1); cp_commit(); }

        #pragma unroll
        for (int k16 = 0; k16 < 2; ++k16) {
            uint32_t af[4][4];
            #pragma unroll
            for (int mi = 0; mi < 4; ++mi) {
                int row = wm * 64 + mi * 16 + (lane & 15);
                int col = k16 * 16 + ((lane >> 4) << 3);
                uint32_t addr = (uint32_t)__cvta_generic_to_shared(&As[st][row * LDS + col]);
                asm volatile("ldmatrix.sync.aligned.m8n8.x4.shared.b16 {%0,%1,%2,%3}, [%4];\n"
                             : "=r"(af[mi][0]), "=r"(af[mi][1]), "=r"(af[mi][2]), "=r"(af[mi][3])
                             : "r"(addr));
            }
            uint32_t bfr[2][4];
            #pragma unroll
            for (int j = 0; j < 2; ++j) {
                int row = wn * 32 + j * 16 + ((lane >> 4) << 3) + (lane & 7);
                int col = k16 * 16 + (((lane >> 3) & 1) << 3);
                uint32_t addr = (uint32_t)__cvta_generic_to_shared(&Bs[st][row * LDS + col]);
                asm volatile("ldmatrix.sync.aligned.m8n8.x4.shared.b16 {%0,%1,%2,%3}, [%4];\n"
                             : "=r"(bfr[j][0]), "=r"(bfr[j][1]), "=r"(bfr[j][2]), "=r"(bfr[j][3])
                             : "r"(addr));
            }
            #pragma unroll
            for (int mi = 0; mi < 4; ++mi)
                #pragma unroll
                for (int ni = 0; ni < 4; ++ni) {
                    uint32_t b0 = bfr[ni >> 1][(ni & 1) * 2];
                    uint32_t b1 = bfr[ni >> 1][(ni & 1) * 2 + 1];
                    asm volatile("mma.sync.aligned.m16n8k16.row.col.f32.bf16.bf16.f32 "
                                 "{%0,%1,%2,%3}, {%4,%5,%6,%7}, {%8,%9}, {%0,%1,%2,%3};\n"
                                 : "+f"(c[mi][ni][0]), "+f"(c[mi][ni][1]),
                                   "+f"(c[mi][ni][2]), "+f"(c[mi][ni][3])
                                 : "r"(af[mi][0]), "r"(af[mi][1]), "r"(af[mi][2]), "r"(af[mi][3]),
                                   "r"(b0), "r"(b1));
                }
        }
        __syncthreads();
        st ^= 1;
    }

    // -------- epilogue --------
    const int g = lane >> 2, t = lane & 3;
    #pragma unroll
    for (int mi = 0; mi < 4; ++mi) {
        #pragma unroll
        for (int ni = 0; ni < 4; ++ni) {
            int col = nBase + wn * 32 + ni * 8 + t * 2;
            #pragma unroll
            for (int half = 0; half < 2; ++half) {
                int m = mBase + wm * 64 + mi * 16 + g + half * 8;
                float v0 = c[mi][ni][half * 2 + 0] + bias[col];
                float v1 = c[mi][ni][half * 2 + 1] + bias[col + 1];
                if (MODE == 0) {
                    __nv_bfloat162 p;
                    p.x = __float2bfloat16(v0); p.y = __float2bfloat16(v1);
                    *reinterpret_cast<__nv_bfloat162*>(outB + (size_t)m * ldc + coff + col) = p;
                } else if (MODE == 1) {
                    if (col < kDI) {
                        __nv_bfloat162 p;
                        p.x = __float2bfloat16(1.f / (1.f + __expf(-v0)));
                        p.y = __float2bfloat16(1.f / (1.f + __expf(-v1)));
                        *reinterpret_cast<__nv_bfloat162*>(outB + (size_t)m * kDI + col) = p;
                    } else {
                        __nv_bfloat162 p;
                        p.x = __float2bfloat16(v0); p.y = __float2bfloat16(v1);
                        *reinterpret_cast<__nv_bfloat162*>(out1 + (size_t)m * kDI + col - kDI) = p;
                    }
                } else if (MODE == 2) {
                    __nv_bfloat162 gp = *reinterpret_cast<const __nv_bfloat162*>(
                        gate + (size_t)m * kDI + col);
                    __nv_bfloat162 p;
                    p.x = __float2bfloat16(v0 * __bfloat162float(gp.x));
                    p.y = __float2bfloat16(v1 * __bfloat162float(gp.y));
                    *reinterpret_cast<__nv_bfloat162*>(outB + (size_t)m * kDI + col) = p;
                } else {
                    const float2 r = *reinterpret_cast<const float2*>(resid + (size_t)m * ldc + col);
                    float2 o; o.x = r.x + v0; o.y = r.y + v1;
                    *reinterpret_cast<float2*>(outF + (size_t)m * ldc + col) = o;
                }
            }
        }
    }
}

// ==================== host side ====================
extern "C" void kernel_launch(void* const* d_in, const int* in_sizes, int n_in,
                              void* d_out, int out_size) {
    const float* x      = (const float*)d_in[0];
    const float* norm_w = (const float*)d_in[1];
    const float* in_w   = (const float*)d_in[2];
    const float* in_b   = (const float*)d_in[3];
    const float* dwa_k  = (const float*)d_in[4];
    const float* dwa_b  = (const float*)d_in[5];
    const float* Amat   = (const float*)d_in[6];
    const float* Bm     = (const float*)d_in[7];
    const float* sym_k  = (const float*)d_in[8];
    const float* sym_b  = (const float*)d_in[9];
    const float* pw_w   = (const float*)d_in[10];
    const float* pw_b   = (const float*)d_in[11];
    const float* ha_w   = (const float*)d_in[12];
    const float* ha_b   = (const float*)d_in[13];
    const float* hb_w   = (const float*)d_in[14];
    const float* hb_b   = (const float*)d_in[15];
    const float* fuse_w = (const float*)d_in[16];
    const float* fuse_b = (const float*)d_in[17];
    const float* out_w  = (const float*)d_in[18];
    const float* out_b  = (const float*)d_in[19];
    float* out = (float*)d_out;

    __nv_bfloat16 *hn, *gateB, *valB, *a1, *b1, *b2, *yB, *y2;
    __nv_bfloat16 *w_in, *w_pw, *w_hb, *w_fuse, *w_out;
    float *a2, *C1;
    cudaGetSymbolAddress((void**)&hn,    g_hn);
    cudaGetSymbolAddress((void**)&gateB, g_gate);
    cudaGetSymbolAddress((void**)&valB,  g_val);
    cudaGetSymbolAddress((void**)&a1,    g_a1);
    cudaGetSymbolAddress((void**)&a2,    g_a2);
    cudaGetSymbolAddress((void**)&C1,    g_C1);
    cudaGetSymbolAddress((void**)&b1,    g_b1);
    cudaGetSymbolAddress((void**)&b2,    g_b2);
    cudaGetSymbolAddress((void**)&yB,    g_y);
    cudaGetSymbolAddress((void**)&y2,    g_y2);
    cudaGetSymbolAddress((void**)&w_in,   g_w_in);
    cudaGetSymbolAddress((void**)&w_pw,   g_w_pw);
    cudaGetSymbolAddress((void**)&w_hb,   g_w_hb);
    cudaGetSymbolAddress((void**)&w_fuse, g_w_fuse);
    cudaGetSymbolAddress((void**)&w_out,  g_w_out);

    // weight conversions (fp32 -> bf16)
    f2bf_kernel<<<4096, 256>>>(in_w,   w_in,   2 * kDI * kD);
    f2bf_kernel<<<4096, 256>>>(pw_w,   w_pw,   kDI * kDI);
    f2bf_kernel<<<2048, 256>>>(hb_w,   w_hb,   (kDI / 2) * kDI);
    f2bf_kernel<<<4096, 256>>>(fuse_w, w_fuse, kDI * kDI);
    f2bf_kernel<<<2048, 256>>>(out_w,  w_out,  kD * kDI);

    // rmsnorm
    rmsnorm_kernel<<<kM, 256>>>(x, norm_w, hn);

    // in-proj: [16384,4096] ; epilogue splits into sigmoid(gate) and val (bf16)
    gemm_bf16<1><<<dim3((2 * kDI) / BN, kM / BM), 256>>>(
        hn, w_in, in_b, kD, 2 * kDI, gateB, valB, nullptr, nullptr, nullptr, kDI, 0);

    // depthwise convs
    dwconv4_kernel<<<(kM * kDI) / 256, 256>>>(valB, dwa_k, dwa_b, a1);
    dwconv9_silu_kernel<<<(kM * kDI) / 256, 256>>>(valB, sym_k, sym_b, b1);

    // low-rank a-path
    lowrank_a2_kernel<<<(kM * 32) / 256, 256>>>(a1, Amat, a2);
    c1_kernel<<<(kDS * 1024 * 32) / 256, 256>>>(Bm, ha_w, C1);

    // pw GEMM: b2 = b1 @ pw_w^T + pw_b
    gemm_bf16<0><<<dim3(kDI / BN, kM / BM), 256>>>(
        b1, w_pw, pw_b, kDI, kDI, b2, nullptr, nullptr, nullptr, nullptr, kDI, 0);

    // y[:, :1024] = a2 @ C1 + ha_b   (rank-16 contraction)
    a4_kernel<<<(kM * 1024) / 256, 256>>>(a2, C1, ha_b, yB);

    // y[:, 1024:] = b2 @ hb_w^T + hb_b
    gemm_bf16<0><<<dim3((kDI / 2) / BN, kM / BM), 256>>>(
        b2, w_hb, hb_b, kDI, kDI / 2, yB, nullptr, nullptr, nullptr, nullptr, kDI, kDI / 2);

    // fuse GEMM with gate multiply epilogue
    gemm_bf16<2><<<dim3(kDI / BN, kM / BM), 256>>>(
        yB, w_fuse, fuse_b, kDI, kDI, y2, nullptr, gateB, nullptr, nullptr, kDI, 0);

    // out GEMM with residual add, fp32 output
    gemm_bf16<3><<<dim3(kD / BN, kM / BM), 256>>>(
        y2, w_out, out_b, kDI, kD, nullptr, nullptr, nullptr, x, out, kD, 0);
}

// round 7
// speedup vs baseline: 1.0498x; 1.0498x over previous
#include <cuda_runtime.h>
#include <cuda_bf16.h>
#include <cstdint>

constexpr int kL  = 4096;
constexpr int kD  = 1024;
constexpr int kDI = 2048;
constexpr int kM  = 4 * kL;           // 16384
constexpr int kDS = 16;

// ---------------- static scratch ----------------
__device__ __align__(256) __nv_bfloat16 g_hn  [(size_t)kM * kD];
__device__ __align__(256) __nv_bfloat16 g_gate[(size_t)kM * kDI];
__device__ __align__(256) __nv_bfloat16 g_val [(size_t)kM * kDI];
__device__ __align__(256) __nv_bfloat16 g_a1  [(size_t)kM * kDI];
__device__ __align__(256) float         g_a2  [(size_t)kM * kDS];
__device__ __align__(256) float         g_C1  [(size_t)kDS * kD];
__device__ __align__(256) __nv_bfloat16 g_b1  [(size_t)kM * kDI];
__device__ __align__(256) __nv_bfloat16 g_b2  [(size_t)kM * kDI];
__device__ __align__(256) __nv_bfloat16 g_y   [(size_t)kM * kDI];
__device__ __align__(256) __nv_bfloat16 g_y2  [(size_t)kM * kDI];
__device__ __align__(256) __nv_bfloat16 g_w_in  [(size_t)2*kDI * kD];
__device__ __align__(256) __nv_bfloat16 g_w_pw  [(size_t)kDI * kDI];
__device__ __align__(256) __nv_bfloat16 g_w_hb  [(size_t)(kDI/2) * kDI];
__device__ __align__(256) __nv_bfloat16 g_w_fuse[(size_t)kDI * kDI];
__device__ __align__(256) __nv_bfloat16 g_w_out [(size_t)kD * kDI];

#define DEVFN __device__ __forceinline__

DEVFN void cp_async16(void* smem, const void* gmem) {
    uint32_t a = (uint32_t)__cvta_generic_to_shared(smem);
    asm volatile("cp.async.cg.shared.global [%0], [%1], 16;" :: "r"(a), "l"(gmem));
}
DEVFN void cp_commit() { asm volatile("cp.async.commit_group;"); }
template<int N> DEVFN void cp_wait_group() { asm volatile("cp.async.wait_group %0;" :: "n"(N)); }

// ---------------- elementwise kernels ----------------
__global__ void f2bf_kernel(const float4* __restrict__ s, uint2* __restrict__ d, int n4) {
    int i = blockIdx.x * blockDim.x + threadIdx.x, st = gridDim.x * blockDim.x;
    for (; i < n4; i += st) {
        float4 v = s[i];
        __nv_bfloat162 lo = __floats2bfloat162_rn(v.x, v.y);
        __nv_bfloat162 hi = __floats2bfloat162_rn(v.z, v.w);
        uint2 o; o.x = *(uint32_t*)&lo; o.y = *(uint32_t*)&hi;
        d[i] = o;
    }
}

__global__ void rmsnorm_kernel(const float* __restrict__ x, const float* __restrict__ w,
                               __nv_bfloat16* __restrict__ out) {
    int m = blockIdx.x;
    const float* xr = x + (size_t)m * kD;
    float ss = 0.f;
    for (int c = threadIdx.x; c < kD; c += 256) { float v = xr[c]; ss += v * v; }
    #pragma unroll
    for (int o = 16; o; o >>= 1) ss += __shfl_xor_sync(~0u, ss, o);
    __shared__ float red[8];
    if ((threadIdx.x & 31) == 0) red[threadIdx.x >> 5] = ss;
    __syncthreads();
    float tot = 0.f;
    #pragma unroll
    for (int i = 0; i < 8; ++i) tot += red[i];
    float sc = rsqrtf(tot * (1.f / kD) + 1e-6f);
    for (int c = threadIdx.x; c < kD; c += 256)
        out[(size_t)m * kD + c] = __float2bfloat16(w[c] * xr[c] * sc);
}

// fused depthwise convs: a1 = conv4(val), b1 = silu(conv9(val))
__global__ void dwconv_fused_kernel(const __nv_bfloat16* __restrict__ val,
                                    const float* __restrict__ k4, const float* __restrict__ b4,
                                    const float* __restrict__ k9, const float* __restrict__ b9,
                                    __nv_bfloat16* __restrict__ a1, __nv_bfloat16* __restrict__ b1) {
    int idx = blockIdx.x * blockDim.x + threadIdx.x;
    int c = idx & (kDI - 1);
    int m = idx >> 11;
    int l = m & (kL - 1);
    float v[9];
    #pragma unroll
    for (int t = 0; t < 9; ++t) {
        int ll = l + t - 4;
        v[t] = (ll >= 0 && ll < kL) ? __bfloat162float(val[(size_t)(m + t - 4) * kDI + c]) : 0.f;
    }
    float a = b4[c];
    #pragma unroll
    for (int t = 0; t < 4; ++t) a += v[t + 3] * k4[c * 4 + t];   // taps at l-1..l+2
    float b = b9[c];
    #pragma unroll
    for (int t = 0; t < 9; ++t) b += v[t] * k9[c * 9 + t];
    a1[idx] = __float2bfloat16(a);
    b1[idx] = __float2bfloat16(b / (1.f + __expf(-b)));
}

__global__ void lowrank_a2_kernel(const __nv_bfloat16* __restrict__ a1,
                                  const float* __restrict__ A, float* __restrict__ a2) {
    int warp = (blockIdx.x * blockDim.x + threadIdx.x) >> 5;
    int lane = threadIdx.x & 31;
    if (warp >= kM) return;
    float acc[kDS];
    #pragma unroll
    for (int s = 0; s < kDS; ++s) acc[s] = 0.f;
    const __nv_bfloat16* row = a1 + (size_t)warp * kDI;
    for (int c = lane; c < kDI; c += 32) {
        float av = __bfloat162float(row[c]);
        const float* Ac = A + (size_t)c * kDS;
        #pragma unroll
        for (int s = 0; s < kDS; ++s) acc[s] += av * Ac[s];
    }
    #pragma unroll
    for (int s = 0; s < kDS; ++s) {
        #pragma unroll
        for (int o = 16; o; o >>= 1) acc[s] += __shfl_xor_sync(~0u, acc[s], o);
    }
    if (lane == 0) {
        #pragma unroll
        for (int s = 0; s < kDS; ++s) a2[(size_t)warp * kDS + s] = acc[s];
    }
}

__global__ void c1_kernel(const float* __restrict__ Bm, const float* __restrict__ ha_w,
                          float* __restrict__ C1) {
    int g = (blockIdx.x * blockDim.x + threadIdx.x) >> 5;
    int lane = threadIdx.x & 31;
    if (g >= kDS * kD) return;
    int s = g >> 10, h = g & 1023;
    float acc = 0.f;
    const float* br = Bm + (size_t)s * kDI;
    const float* hr = ha_w + (size_t)h * kDI;
    for (int d = lane; d < kDI; d += 32) acc += br[d] * hr[d];
    #pragma unroll
    for (int o = 16; o; o >>= 1) acc += __shfl_xor_sync(~0u, acc, o);
    if (lane == 0) C1[(size_t)s * kD + h] = acc;
}

__global__ void a4_kernel(const float* __restrict__ a2, const float* __restrict__ C1,
                          const float* __restrict__ ha_b, __nv_bfloat16* __restrict__ y) {
    int idx = blockIdx.x * blockDim.x + threadIdx.x;
    int h = idx & 1023, m = idx >> 10;
    float acc = ha_b[h];
    const float* ar = a2 + (size_t)m * kDS;
    #pragma unroll
    for (int s = 0; s < kDS; ++s) acc += ar[s] * C1[(size_t)s * kD + h];
    y[(size_t)m * kDI + h] = __float2bfloat16(acc);
}

// ==================== bf16 mma.sync GEMM, 128x256x64, 3-stage ====================
// C[M,N] = A[M,K] @ B[N,K]^T + bias.  8 warps (2x4), warp tile 64x64.
// MODE 0: bf16 -> out0[m*ldc + n]
// MODE 1: sigmoid -> out0 if col<kDI else raw -> out1 (col-kDI); ldc=kDI
// MODE 2: (acc+bias)*gate -> out0
// MODE 3: outF = resid + acc + bias (fp32)
constexpr int BM = 128, BN = 256, BK = 64, LDS = BK + 8;     // 72 elems/row
constexpr int NROWS = BM + BN;                                // 384
constexpr int NSTG  = 3;
constexpr int STG_ELEMS = NROWS * LDS;                        // 27648
constexpr size_t SMEM_G = (size_t)NSTG * STG_ELEMS * 2;       // 165888 B

template<int MODE>
__global__ __launch_bounds__(256, 1)
void gemm_bf16(const __nv_bfloat16* __restrict__ Ag,
               const __nv_bfloat16* __restrict__ Bg,
               const float* __restrict__ bias,
               int K,
               __nv_bfloat16* __restrict__ out0,
               __nv_bfloat16* __restrict__ out1,
               const __nv_bfloat16* __restrict__ gate,
               const float* __restrict__ resid,
               float* __restrict__ outF,
               int ldc) {
    extern __shared__ __align__(16) __nv_bfloat16 sm[];
    const int tid  = threadIdx.x;
    const int lane = tid & 31;
    const int warp = tid >> 5;
    const int wm = warp >> 2, wn = warp & 3;          // 2 x 4 warp grid
    const int mBase = blockIdx.y * BM;
    const int nBase = blockIdx.x * BN;
    const int KT = K / BK;

    float c[4][8][4];
    #pragma unroll
    for (int i = 0; i < 4; ++i)
        #pragma unroll
        for (int j = 0; j < 8; ++j)
            #pragma unroll
            for (int q = 0; q < 4; ++q) c[i][j][q] = 0.f;

    auto load_tile = [&](int kt, int st) {
        __nv_bfloat16* dst = sm + (size_t)st * STG_ELEMS;
        int k0 = kt * BK;
        #pragma unroll
        for (int i = 0; i < 12; ++i) {
            int lin = tid + i * 256;                  // 0..3071
            int r   = lin >> 3;                       // 0..383
            int cc  = (lin & 7) << 3;                 // 0..56
            const __nv_bfloat16* src = (r < BM)
                ? Ag + (size_t)(mBase + r) * K + k0 + cc
                : Bg + (size_t)(nBase + r - BM) * K + k0 + cc;
            cp_async16(dst + r * LDS + cc, src);
        }
        cp_commit();
    };

    load_tile(0, 0);
    load_tile(1, 1);

    for (int kt = 0; kt < KT; ++kt) {
        cp_wait_group<1>();
        __syncthreads();
        int st = kt % NSTG;
        if (kt + 2 < KT) load_tile(kt + 2, (kt + 2) % NSTG);
        else cp_commit();                              // keep group count uniform
        const __nv_bfloat16* As = sm + (size_t)st * STG_ELEMS;
        const __nv_bfloat16* Bs = As + BM * LDS;

        #pragma unroll
        for (int k16 = 0; k16 < 4; ++k16) {
            uint32_t af[4][4];
            #pragma unroll
            for (int mi = 0; mi < 4; ++mi) {
                int row = wm * 64 + mi * 16 + (lane & 15);
                int col = k16 * 16 + ((lane >> 4) << 3);
                uint32_t addr = (uint32_t)__cvta_generic_to_shared(&As[row * LDS + col]);
                asm volatile("ldmatrix.sync.aligned.m8n8.x4.shared.b16 {%0,%1,%2,%3}, [%4];"
                             : "=r"(af[mi][0]), "=r"(af[mi][1]), "=r"(af[mi][2]), "=r"(af[mi][3])
                             : "r"(addr));
            }
            uint32_t bfr[4][4];
            #pragma unroll
            for (int j = 0; j < 4; ++j) {
                int row = wn * 64 + j * 16 + ((lane >> 4) << 3) + (lane & 7);
                int col = k16 * 16 + (((lane >> 3) & 1) << 3);
                uint32_t addr = (uint32_t)__cvta_generic_to_shared(&Bs[row * LDS + col]);
                asm volatile("ldmatrix.sync.aligned.m8n8.x4.shared.b16 {%0,%1,%2,%3}, [%4];"
                             : "=r"(bfr[j][0]), "=r"(bfr[j][1]), "=r"(bfr[j][2]), "=r"(bfr[j][3])
                             : "r"(addr));
            }
            #pragma unroll
            for (int mi = 0; mi < 4; ++mi)
                #pragma unroll
                for (int ni = 0; ni < 8; ++ni) {
                    uint32_t b0 = bfr[ni >> 1][(ni & 1) * 2];
                    uint32_t b1 = bfr[ni >> 1][(ni & 1) * 2 + 1];
                    asm volatile("mma.sync.aligned.m16n8k16.row.col.f32.bf16.bf16.f32 "
                                 "{%0,%1,%2,%3}, {%4,%5,%6,%7}, {%8,%9}, {%0,%1,%2,%3};"
                                 : "+f"(c[mi][ni][0]), "+f"(c[mi][ni][1]),
                                   "+f"(c[mi][ni][2]), "+f"(c[mi][ni][3])
                                 : "r"(af[mi][0]), "r"(af[mi][1]), "r"(af[mi][2]), "r"(af[mi][3]),
                                   "r"(b0), "r"(b1));
                }
        }
        __syncthreads();
    }

    // -------- epilogue --------
    const int g = lane >> 2, t = lane & 3;
    #pragma unroll
    for (int mi = 0; mi < 4; ++mi) {
        #pragma unroll
        for (int ni = 0; ni < 8; ++ni) {
            int col = nBase + wn * 64 + ni * 8 + t * 2;
            #pragma unroll
            for (int half = 0; half < 2; ++half) {
                int m = mBase + wm * 64 + mi * 16 + g + half * 8;
                float v0 = c[mi][ni][half * 2 + 0] + bias[col];
                float v1 = c[mi][ni][half * 2 + 1] + bias[col + 1];
                if (MODE == 0) {
                    __nv_bfloat162 p;
                    p.x = __float2bfloat16(v0); p.y = __float2bfloat16(v1);
                    *reinterpret_cast<__nv_bfloat162*>(out0 + (size_t)m * ldc + col) = p;
                } else if (MODE == 1) {
                    if (col < kDI) {
                        __nv_bfloat162 p;
                        p.x = __float2bfloat16(1.f / (1.f + __expf(-v0)));
                        p.y = __float2bfloat16(1.f / (1.f + __expf(-v1)));
                        *reinterpret_cast<__nv_bfloat162*>(out0 + (size_t)m * kDI + col) = p;
                    } else {
                        __nv_bfloat162 p;
                        p.x = __float2bfloat16(v0); p.y = __float2bfloat16(v1);
                        *reinterpret_cast<__nv_bfloat162*>(out1 + (size_t)m * kDI + col - kDI) = p;
                    }
                } else if (MODE == 2) {
                    __nv_bfloat162 gp = *reinterpret_cast<const __nv_bfloat162*>(
                        gate + (size_t)m * kDI + col);
                    __nv_bfloat162 p;
                    p.x = __float2bfloat16(v0 * __bfloat162float(gp.x));
                    p.y = __float2bfloat16(v1 * __bfloat162float(gp.y));
                    *reinterpret_cast<__nv_bfloat162*>(out0 + (size_t)m * kDI + col) = p;
                } else {
                    const float2 r = *reinterpret_cast<const float2*>(resid + (size_t)m * ldc + col);
                    float2 o; o.x = r.x + v0; o.y = r.y + v1;
                    *reinterpret_cast<float2*>(outF + (size_t)m * ldc + col) = o;
                }
            }
        }
    }
}

// ==================== host ====================
extern "C" void kernel_launch(void* const* d_in, const int* in_sizes, int n_in,
                              void* d_out, int out_size) {
    const float* x      = (const float*)d_in[0];
    const float* norm_w = (const float*)d_in[1];
    const float* in_w   = (const float*)d_in[2];
    const float* in_b   = (const float*)d_in[3];
    const float* dwa_k  = (const float*)d_in[4];
    const float* dwa_b  = (const float*)d_in[5];
    const float* Amat   = (const float*)d_in[6];
    const float* Bm     = (const float*)d_in[7];
    const float* sym_k  = (const float*)d_in[8];
    const float* sym_b  = (const float*)d_in[9];
    const float* pw_w   = (const float*)d_in[10];
    const float* pw_b   = (const float*)d_in[11];
    const float* ha_w   = (const float*)d_in[12];
    const float* ha_b   = (const float*)d_in[13];
    const float* hb_w   = (const float*)d_in[14];
    const float* hb_b   = (const float*)d_in[15];
    const float* fuse_w = (const float*)d_in[16];
    const float* fuse_b = (const float*)d_in[17];
    const float* out_w  = (const float*)d_in[18];
    const float* out_b  = (const float*)d_in[19];
    float* out = (float*)d_out;

    __nv_bfloat16 *hn, *gateB, *valB, *a1, *b1, *b2, *yB, *y2;
    __nv_bfloat16 *w_in, *w_pw, *w_hb, *w_fuse, *w_out;
    float *a2, *C1;
    cudaGetSymbolAddress((void**)&hn,    g_hn);
    cudaGetSymbolAddress((void**)&gateB, g_gate);
    cudaGetSymbolAddress((void**)&valB,  g_val);
    cudaGetSymbolAddress((void**)&a1,    g_a1);
    cudaGetSymbolAddress((void**)&a2,    g_a2);
    cudaGetSymbolAddress((void**)&C1,    g_C1);
    cudaGetSymbolAddress((void**)&b1,    g_b1);
    cudaGetSymbolAddress((void**)&b2,    g_b2);
    cudaGetSymbolAddress((void**)&yB,    g_y);
    cudaGetSymbolAddress((void**)&y2,    g_y2);
    cudaGetSymbolAddress((void**)&w_in,   g_w_in);
    cudaGetSymbolAddress((void**)&w_pw,   g_w_pw);
    cudaGetSymbolAddress((void**)&w_hb,   g_w_hb);
    cudaGetSymbolAddress((void**)&w_fuse, g_w_fuse);
    cudaGetSymbolAddress((void**)&w_out,  g_w_out);

    cudaFuncSetAttribute(gemm_bf16<0>, cudaFuncAttributeMaxDynamicSharedMemorySize, (int)SMEM_G);
    cudaFuncSetAttribute(gemm_bf16<1>, cudaFuncAttributeMaxDynamicSharedMemorySize, (int)SMEM_G);
    cudaFuncSetAttribute(gemm_bf16<2>, cudaFuncAttributeMaxDynamicSharedMemorySize, (int)SMEM_G);
    cudaFuncSetAttribute(gemm_bf16<3>, cudaFuncAttributeMaxDynamicSharedMemorySize, (int)SMEM_G);

    // fp32 -> bf16 weight conversion
    f2bf_kernel<<<1024, 256>>>((const float4*)in_w,   (uint2*)w_in,   (2*kDI*kD)/4);
    f2bf_kernel<<<1024, 256>>>((const float4*)pw_w,   (uint2*)w_pw,   (kDI*kDI)/4);
    f2bf_kernel<<<512,  256>>>((const float4*)hb_w,   (uint2*)w_hb,   ((kDI/2)*kDI)/4);
    f2bf_kernel<<<1024, 256>>>((const float4*)fuse_w, (uint2*)w_fuse, (kDI*kDI)/4);
    f2bf_kernel<<<512,  256>>>((const float4*)out_w,  (uint2*)w_out,  (kD*kDI)/4);

    rmsnorm_kernel<<<kM, 256>>>(x, norm_w, hn);

    // in-proj: sigmoid(gate)/val split
    gemm_bf16<1><<<dim3((2*kDI)/BN, kM/BM), 256, SMEM_G>>>(
        hn, w_in, in_b, kD, gateB, valB, nullptr, nullptr, nullptr, kDI);

    // fused depthwise convs (reads val once)
    dwconv_fused_kernel<<<(kM*kDI)/256, 256>>>(valB, dwa_k, dwa_b, sym_k, sym_b, a1, b1);

    // low-rank a-path
    lowrank_a2_kernel<<<(kM*32)/256, 256>>>(a1, Amat, a2);
    c1_kernel<<<(kDS*kD*32)/256, 256>>>(Bm, ha_w, C1);

    // pw: b2 = b1 @ pw_w^T + pw_b
    gemm_bf16<0><<<dim3(kDI/BN, kM/BM), 256, SMEM_G>>>(
        b1, w_pw, pw_b, kDI, b2, nullptr, nullptr, nullptr, nullptr, kDI);

    // y[:, :1024] = a2 @ C1 + ha_b (rank-16)
    a4_kernel<<<(kM*kD)/256, 256>>>(a2, C1, ha_b, yB);

    // y[:, 1024:] = b2 @ hb_w^T + hb_b  (pointer offset, ldc=kDI)
    gemm_bf16<0><<<dim3((kDI/2)/BN, kM/BM), 256, SMEM_G>>>(
        b2, w_hb, hb_b, kDI, yB + kDI/2, nullptr, nullptr, nullptr, nullptr, kDI);

    // fuse with gate-multiply epilogue
    gemm_bf16<2><<<dim3(kDI/BN, kM/BM), 256, SMEM_G>>>(
        yB, w_fuse, fuse_b, kDI, y2, nullptr, gateB, nullptr, nullptr, kDI);

    // out-proj with residual add, fp32 out
    gemm_bf16<3><<<dim3(kD/BN, kM/BM), 256, SMEM_G>>>(
        y2, w_out, out_b, kDI, nullptr, nullptr, nullptr, x, out, kD);
}

// round 9
// speedup vs baseline: 1.2244x; 1.1664x over previous
#include <cuda_runtime.h>
#include <cuda_bf16.h>
#include <cstdint>

constexpr int kL  = 4096;
constexpr int kD  = 1024;
constexpr int kDI = 2048;
constexpr int kM  = 4 * kL;           // 16384
constexpr int kDS = 16;

// ---------------- static scratch ----------------
__device__ __align__(256) __nv_bfloat16 g_hn  [(size_t)kM * kD];
__device__ __align__(256) __nv_bfloat16 g_gate[(size_t)kM * kDI];
__device__ __align__(256) __nv_bfloat16 g_val [(size_t)kM * kDI];
__device__ __align__(256) __nv_bfloat16 g_a1  [(size_t)kM * kDI];
__device__ __align__(256) float         g_a2  [(size_t)kM * kDS];
__device__ __align__(256) float         g_C1  [(size_t)kDS * kD];
__device__ __align__(256) float         g_C2  [(size_t)kDS * kDI];
__device__ __align__(256) __nv_bfloat16 g_b1  [(size_t)kM * kDI];
__device__ __align__(256) __nv_bfloat16 g_az  [(size_t)kM * kDI];
__device__ __align__(256) __nv_bfloat16 g_y2  [(size_t)kM * kDI];
__device__ __align__(256) __nv_bfloat16 g_w_in  [(size_t)2*kDI * kD];
__device__ __align__(256) __nv_bfloat16 g_w_fuse[(size_t)kDI * kDI];
__device__ __align__(256) __nv_bfloat16 g_w_out [(size_t)kD * kDI];
__device__ __align__(256) __nv_bfloat16 g_hbT [(size_t)kDI * kD];    // hb_w^T  [2048,1024]
__device__ __align__(256) __nv_bfloat16 g_pwT [(size_t)kDI * kDI];   // pw_w^T  [2048,2048]
__device__ __align__(256) __nv_bfloat16 g_W2  [(size_t)kDI * kDI];   // F2 @ hb_w
__device__ __align__(256) __nv_bfloat16 g_W3  [(size_t)kDI * kDI];   // W2 @ pw_w
__device__ float g_zb[kDI];                                           // folded bias
__device__ float g_zero_bias[kDI];                                    // zeros (static init)

#define DEVFN __device__ __forceinline__

DEVFN void cp_async16(void* smem, const void* gmem) {
    uint32_t a = (uint32_t)__cvta_generic_to_shared(smem);
    asm volatile("cp.async.cg.shared.global [%0], [%1], 16;" :: "r"(a), "l"(gmem));
}
DEVFN void cp_commit() { asm volatile("cp.async.commit_group;"); }
template<int N> DEVFN void cp_wait_group() { asm volatile("cp.async.wait_group %0;" :: "n"(N)); }

// ---------------- elementwise kernels ----------------
__global__ void f2bf_kernel(const float4* __restrict__ s, uint2* __restrict__ d, int n4) {
    int i = blockIdx.x * blockDim.x + threadIdx.x, st = gridDim.x * blockDim.x;
    for (; i < n4; i += st) {
        float4 v = s[i];
        __nv_bfloat162 lo = __floats2bfloat162_rn(v.x, v.y);
        __nv_bfloat162 hi = __floats2bfloat162_rn(v.z, v.w);
        uint2 o; o.x = *(uint32_t*)&lo; o.y = *(uint32_t*)&hi;
        d[i] = o;
    }
}

// transpose fp32 [R,C] -> bf16 [C,R]
__global__ void transpose_f2bf(const float* __restrict__ src, __nv_bfloat16* __restrict__ dst,
                               int R, int C) {
    __shared__ float t[32][33];
    int c0 = blockIdx.x * 32, r0 = blockIdx.y * 32;
    int x = threadIdx.x;
    #pragma unroll
    for (int y = threadIdx.y; y < 32; y += 8)
        t[y][x] = src[(size_t)(r0 + y) * C + c0 + x];
    __syncthreads();
    #pragma unroll
    for (int y = threadIdx.y; y < 32; y += 8)
        dst[(size_t)(c0 + y) * R + r0 + x] = __float2bfloat16(t[x][y]);
}

__global__ void rmsnorm_kernel(const float* __restrict__ x, const float* __restrict__ w,
                               __nv_bfloat16* __restrict__ out) {
    int m = blockIdx.x;
    const float* xr = x + (size_t)m * kD;
    float ss = 0.f;
    for (int c = threadIdx.x; c < kD; c += 256) { float v = xr[c]; ss += v * v; }
    #pragma unroll
    for (int o = 16; o; o >>= 1) ss += __shfl_xor_sync(~0u, ss, o);
    __shared__ float red[8];
    if ((threadIdx.x & 31) == 0) red[threadIdx.x >> 5] = ss;
    __syncthreads();
    float tot = 0.f;
    #pragma unroll
    for (int i = 0; i < 8; ++i) tot += red[i];
    float sc = rsqrtf(tot * (1.f / kD) + 1e-6f);
    for (int c = threadIdx.x; c < kD; c += 256)
        out[(size_t)m * kD + c] = __float2bfloat16(w[c] * xr[c] * sc);
}

// fused depthwise convs: a1 = conv4(val), b1 = silu(conv9(val))
__global__ void dwconv_fused_kernel(const __nv_bfloat16* __restrict__ val,
                                    const float* __restrict__ k4, const float* __restrict__ b4,
                                    const float* __restrict__ k9, const float* __restrict__ b9,
                                    __nv_bfloat16* __restrict__ a1, __nv_bfloat16* __restrict__ b1) {
    int idx = blockIdx.x * blockDim.x + threadIdx.x;
    int c = idx & (kDI - 1);
    int m = idx >> 11;
    int l = m & (kL - 1);
    float v[9];
    #pragma unroll
    for (int t = 0; t < 9; ++t) {
        int ll = l + t - 4;
        v[t] = (ll >= 0 && ll < kL) ? __bfloat162float(val[(size_t)(m + t - 4) * kDI + c]) : 0.f;
    }
    float a = b4[c];
    #pragma unroll
    for (int t = 0; t < 4; ++t) a += v[t + 3] * k4[c * 4 + t];
    float b = b9[c];
    #pragma unroll
    for (int t = 0; t < 9; ++t) b += v[t] * k9[c * 9 + t];
    a1[idx] = __float2bfloat16(a);
    b1[idx] = __float2bfloat16(b / (1.f + __expf(-b)));
}

__global__ void lowrank_a2_kernel(const __nv_bfloat16* __restrict__ a1,
                                  const float* __restrict__ A, float* __restrict__ a2) {
    int warp = (blockIdx.x * blockDim.x + threadIdx.x) >> 5;
    int lane = threadIdx.x & 31;
    if (warp >= kM) return;
    float acc[kDS];
    #pragma unroll
    for (int s = 0; s < kDS; ++s) acc[s] = 0.f;
    const __nv_bfloat16* row = a1 + (size_t)warp * kDI;
    for (int c = lane; c < kDI; c += 32) {
        float av = __bfloat162float(row[c]);
        const float* Ac = A + (size_t)c * kDS;
        #pragma unroll
        for (int s = 0; s < kDS; ++s) acc[s] += av * Ac[s];
    }
    #pragma unroll
    for (int s = 0; s < kDS; ++s) {
        #pragma unroll
        for (int o = 16; o; o >>= 1) acc[s] += __shfl_xor_sync(~0u, acc[s], o);
    }
    if (lane == 0) {
        #pragma unroll
        for (int s = 0; s < kDS; ++s) a2[(size_t)warp * kDS + s] = acc[s];
    }
}

// C1[s,h] = sum_d Bm[s,d] * ha_w[h,d]   (fp32, [16,1024])
__global__ void c1_kernel(const float* __restrict__ Bm, const float* __restrict__ ha_w,
                          float* __restrict__ C1) {
    int g = (blockIdx.x * blockDim.x + threadIdx.x) >> 5;
    int lane = threadIdx.x & 31;
    if (g >= kDS * kD) return;
    int s = g >> 10, h = g & 1023;
    float acc = 0.f;
    const float* br = Bm + (size_t)s * kDI;
    const float* hr = ha_w + (size_t)h * kDI;
    for (int d = lane; d < kDI; d += 32) acc += br[d] * hr[d];
    #pragma unroll
    for (int o = 16; o; o >>= 1) acc += __shfl_xor_sync(~0u, acc, o);
    if (lane == 0) C1[(size_t)s * kD + h] = acc;
}

// C2[s,o] = sum_h C1[s,h] * fuse_w[o,h]   (F1 slice; fp32, [16,2048])
__global__ void c2_kernel(const float* __restrict__ C1, const float* __restrict__ fuse_w,
                          float* __restrict__ C2) {
    int g = (blockIdx.x * blockDim.x + threadIdx.x) >> 5;
    int lane = threadIdx.x & 31;
    if (g >= kDS * kDI) return;
    int s = g >> 11, o = g & (kDI - 1);
    float acc = 0.f;
    const float* cr = C1 + (size_t)s * kD;
    const float* fr = fuse_w + (size_t)o * kDI;
    for (int h = lane; h < kD; h += 32) acc += cr[h] * fr[h];
    #pragma unroll
    for (int q = 16; q; q >>= 1) acc += __shfl_xor_sync(~0u, acc, q);
    if (lane == 0) C2[(size_t)s * kDI + o] = acc;
}

// zb[o] = fuse_b[o] + sum_h ha_b[h]F1[o,h] + sum_h hb_b[h]F2[o,h] + sum_d pw_b[d]W2[o,d]
__global__ void zbias_kernel(const float* __restrict__ fuse_b, const float* __restrict__ ha_b,
                             const float* __restrict__ hb_b, const float* __restrict__ pw_b,
                             const float* __restrict__ fuse_w, const __nv_bfloat16* __restrict__ W2,
                             float* __restrict__ zb) {
    int o = (blockIdx.x * blockDim.x + threadIdx.x) >> 5;
    int lane = threadIdx.x & 31;
    if (o >= kDI) return;
    float acc = 0.f;
    const float* fr = fuse_w + (size_t)o * kDI;
    for (int h = lane; h < kD; h += 32) acc += ha_b[h] * fr[h] + hb_b[h] * fr[kD + h];
    const __nv_bfloat16* wr = W2 + (size_t)o * kDI;
    for (int d = lane; d < kDI; d += 32) acc += pw_b[d] * __bfloat162float(wr[d]);
    #pragma unroll
    for (int q = 16; q; q >>= 1) acc += __shfl_xor_sync(~0u, acc, q);
    if (lane == 0) zb[o] = fuse_b[o] + acc;
}

// az[m,o] = sum_s a2[m,s] * C2[s,o]   (bf16 out)
__global__ void aadd_kernel(const float* __restrict__ a2, const float* __restrict__ C2,
                            __nv_bfloat16* __restrict__ az) {
    int idx = blockIdx.x * blockDim.x + threadIdx.x;
    int o = idx & (kDI - 1), m = idx >> 11;
    float acc = 0.f;
    const float* ar = a2 + (size_t)m * kDS;
    #pragma unroll
    for (int s = 0; s < kDS; ++s) acc += ar[s] * C2[(size_t)s * kDI + o];
    az[idx] = __float2bfloat16(acc);
}

// ==================== bf16 mma.sync GEMM, 128x256x64, 3-stage ====================
// C[M,N] = A[M,K] @ B[N,K]^T + bias (A row stride lda, B row stride ldb)
// MODE 0: bf16 -> out0[m*ldc + n]
// MODE 1: sigmoid -> out0 if col<kDI else raw -> out1 (col-kDI); ldc=kDI
// MODE 3: outF = resid + acc + bias (fp32)
// MODE 4: bf16 -> out0 = (acc + bias + aux[m,col]) * gate[m,col]
constexpr int BM = 128, BN = 256, BK = 64, LDS = BK + 8;
constexpr int NROWS = BM + BN;
constexpr int NSTG  = 3;
constexpr int STG_ELEMS = NROWS * LDS;
constexpr size_t SMEM_G = (size_t)NSTG * STG_ELEMS * 2;     // 165888 B

template<int MODE>
__global__ __launch_bounds__(256, 1)
void gemm_bf16(const __nv_bfloat16* __restrict__ Ag,
               const __nv_bfloat16* __restrict__ Bg,
               const float* __restrict__ bias,
               int K, int lda, int ldb,
               __nv_bfloat16* __restrict__ out0,
               __nv_bfloat16* __restrict__ out1,
               const __nv_bfloat16* __restrict__ gate,
               const __nv_bfloat16* __restrict__ aux,
               const float* __restrict__ resid,
               float* __restrict__ outF,
               int ldc) {
    extern __shared__ __align__(16) __nv_bfloat16 sm[];
    const int tid  = threadIdx.x;
    const int lane = tid & 31;
    const int warp = tid >> 5;
    const int wm = warp >> 2, wn = warp & 3;
    const int mBase = blockIdx.y * BM;
    const int nBase = blockIdx.x * BN;
    const int KT = K / BK;

    float c[4][8][4];
    #pragma unroll
    for (int i = 0; i < 4; ++i)
        #pragma unroll
        for (int j = 0; j < 8; ++j)
            #pragma unroll
            for (int q = 0; q < 4; ++q) c[i][j][q] = 0.f;

    auto load_tile = [&](int kt, int st) {
        __nv_bfloat16* dst = sm + (size_t)st * STG_ELEMS;
        int k0 = kt * BK;
        #pragma unroll
        for (int i = 0; i < 12; ++i) {
            int lin = tid + i * 256;
            int r   = lin >> 3;
            int cc  = (lin & 7) << 3;
            const __nv_bfloat16* src = (r < BM)
                ? Ag + (size_t)(mBase + r) * lda + k0 + cc
                : Bg + (size_t)(nBase + r - BM) * ldb + k0 + cc;
            cp_async16(dst + r * LDS + cc, src);
        }
        cp_commit();
    };

    load_tile(0, 0);
    load_tile(1, 1);

    for (int kt = 0; kt < KT; ++kt) {
        cp_wait_group<1>();
        __syncthreads();
        int st = kt % NSTG;
        if (kt + 2 < KT) load_tile(kt + 2, (kt + 2) % NSTG);
        else cp_commit();
        const __nv_bfloat16* As = sm + (size_t)st * STG_ELEMS;
        const __nv_bfloat16* Bs = As + BM * LDS;

        #pragma unroll
        for (int k16 = 0; k16 < 4; ++k16) {
            uint32_t af[4][4];
            #pragma unroll
            for (int mi = 0; mi < 4; ++mi) {
                int row = wm * 64 + mi * 16 + (lane & 15);
                int col = k16 * 16 + ((lane >> 4) << 3);
                uint32_t addr = (uint32_t)__cvta_generic_to_shared(&As[row * LDS + col]);
                asm volatile("ldmatrix.sync.aligned.m8n8.x4.shared.b16 {%0,%1,%2,%3}, [%4];"
                             : "=r"(af[mi][0]), "=r"(af[mi][1]), "=r"(af[mi][2]), "=r"(af[mi][3])
                             : "r"(addr));
            }
            uint32_t bfr[4][4];
            #pragma unroll
            for (int j = 0; j < 4; ++j) {
                int row = wn * 64 + j * 16 + ((lane >> 4) << 3) + (lane & 7);
                int col = k16 * 16 + (((lane >> 3) & 1) << 3);
                uint32_t addr = (uint32_t)__cvta_generic_to_shared(&Bs[row * LDS + col]);
                asm volatile("ldmatrix.sync.aligned.m8n8.x4.shared.b16 {%0,%1,%2,%3}, [%4];"
                             : "=r"(bfr[j][0]), "=r"(bfr[j][1]), "=r"(bfr[j][2]), "=r"(bfr[j][3])
                             : "r"(addr));
            }
            #pragma unroll
            for (int mi = 0; mi < 4; ++mi)
                #pragma unroll
                for (int ni = 0; ni < 8; ++ni) {
                    uint32_t b0 = bfr[ni >> 1][(ni & 1) * 2];
                    uint32_t b1 = bfr[ni >> 1][(ni & 1) * 2 + 1];
                    asm volatile("mma.sync.aligned.m16n8k16.row.col.f32.bf16.bf16.f32 "
                                 "{%0,%1,%2,%3}, {%4,%5,%6,%7}, {%8,%9}, {%0,%1,%2,%3};"
                                 : "+f"(c[mi][ni][0]), "+f"(c[mi][ni][1]),
                                   "+f"(c[mi][ni][2]), "+f"(c[mi][ni][3])
                                 : "r"(af[mi][0]), "r"(af[mi][1]), "r"(af[mi][2]), "r"(af[mi][3]),
                                   "r"(b0), "r"(b1));
                }
        }
        __syncthreads();
    }

    // -------- epilogue --------
    const int g = lane >> 2, t = lane & 3;
    #pragma unroll
    for (int mi = 0; mi < 4; ++mi) {
        #pragma unroll
        for (int ni = 0; ni < 8; ++ni) {
            int col = nBase + wn * 64 + ni * 8 + t * 2;
            #pragma unroll
            for (int half = 0; half < 2; ++half) {
                int m = mBase + wm * 64 + mi * 16 + g + half * 8;
                float v0 = c[mi][ni][half * 2 + 0] + bias[col];
                float v1 = c[mi][ni][half * 2 + 1] + bias[col + 1];
                if (MODE == 0) {
                    __nv_bfloat162 p;
                    p.x = __float2bfloat16(v0); p.y = __float2bfloat16(v1);
                    *reinterpret_cast<__nv_bfloat162*>(out0 + (size_t)m * ldc + col) = p;
                } else if (MODE == 1) {
                    if (col < kDI) {
                        __nv_bfloat162 p;
                        p.x = __float2bfloat16(1.f / (1.f + __expf(-v0)));
                        p.y = __float2bfloat16(1.f / (1.f + __expf(-v1)));
                        *reinterpret_cast<__nv_bfloat162*>(out0 + (size_t)m * kDI + col) = p;
                    } else {
                        __nv_bfloat162 p;
                        p.x = __float2bfloat16(v0); p.y = __float2bfloat16(v1);
                        *reinterpret_cast<__nv_bfloat162*>(out1 + (size_t)m * kDI + col - kDI) = p;
                    }
                } else if (MODE == 4) {
                    __nv_bfloat162 gp = *reinterpret_cast<const __nv_bfloat162*>(
                        gate + (size_t)m * kDI + col);
                    __nv_bfloat162 ap = *reinterpret_cast<const __nv_bfloat162*>(
                        aux + (size_t)m * kDI + col);
                    float2 fg = __bfloat1622float2(gp);
                    float2 fa = __bfloat1622float2(ap);
                    __nv_bfloat162 p;
                    p.x = __float2bfloat16((v0 + fa.x) * fg.x);
                    p.y = __float2bfloat16((v1 + fa.y) * fg.y);
                    *reinterpret_cast<__nv_bfloat162*>(out0 + (size_t)m * kDI + col) = p;
                } else {
                    const float2 r = *reinterpret_cast<const float2*>(resid + (size_t)m * ldc + col);
                    float2 o; o.x = r.x + v0; o.y = r.y + v1;
                    *reinterpret_cast<float2*>(outF + (size_t)m * ldc + col) = o;
                }
            }
        }
    }
}

// ==================== host ====================
extern "C" void kernel_launch(void* const* d_in, const int* in_sizes, int n_in,
                              void* d_out, int out_size) {
    const float* x      = (const float*)d_in[0];
    const float* norm_w = (const float*)d_in[1];
    const float* in_w   = (const float*)d_in[2];
    const float* in_b   = (const float*)d_in[3];
    const float* dwa_k  = (const float*)d_in[4];
    const float* dwa_b  = (const float*)d_in[5];
    const float* Amat   = (const float*)d_in[6];
    const float* Bm     = (const float*)d_in[7];
    const float* sym_k  = (const float*)d_in[8];
    const float* sym_b  = (const float*)d_in[9];
    const float* pw_w   = (const float*)d_in[10];
    const float* pw_b   = (const float*)d_in[11];
    const float* ha_w   = (const float*)d_in[12];
    const float* ha_b   = (const float*)d_in[13];
    const float* hb_w   = (const float*)d_in[14];
    const float* hb_b   = (const float*)d_in[15];
    const float* fuse_w = (const float*)d_in[16];
    const float* fuse_b = (const float*)d_in[17];
    const float* out_w  = (const float*)d_in[18];
    const float* out_b  = (const float*)d_in[19];
    float* out = (float*)d_out;

    __nv_bfloat16 *hn, *gateB, *valB, *a1, *b1, *az, *y2;
    __nv_bfloat16 *w_in, *w_fuse, *w_out, *hbT, *pwT, *W2, *W3;
    float *a2, *C1, *C2, *zb, *zero_b;
    cudaGetSymbolAddress((void**)&hn,    g_hn);
    cudaGetSymbolAddress((void**)&gateB, g_gate);
    cudaGetSymbolAddress((void**)&valB,  g_val);
    cudaGetSymbolAddress((void**)&a1,    g_a1);
    cudaGetSymbolAddress((void**)&a2,    g_a2);
    cudaGetSymbolAddress((void**)&C1,    g_C1);
    cudaGetSymbolAddress((void**)&C2,    g_C2);
    cudaGetSymbolAddress((void**)&b1,    g_b1);
    cudaGetSymbolAddress((void**)&az,    g_az);
    cudaGetSymbolAddress((void**)&y2,    g_y2);
    cudaGetSymbolAddress((void**)&w_in,   g_w_in);
    cudaGetSymbolAddress((void**)&w_fuse, g_w_fuse);
    cudaGetSymbolAddress((void**)&w_out,  g_w_out);
    cudaGetSymbolAddress((void**)&hbT,    g_hbT);
    cudaGetSymbolAddress((void**)&pwT,    g_pwT);
    cudaGetSymbolAddress((void**)&W2,     g_W2);
    cudaGetSymbolAddress((void**)&W3,     g_W3);
    cudaGetSymbolAddress((void**)&zb,     g_zb);
    cudaGetSymbolAddress((void**)&zero_b, g_zero_bias);

    cudaFuncSetAttribute(gemm_bf16<0>, cudaFuncAttributeMaxDynamicSharedMemorySize, (int)SMEM_G);
    cudaFuncSetAttribute(gemm_bf16<1>, cudaFuncAttributeMaxDynamicSharedMemorySize, (int)SMEM_G);
    cudaFuncSetAttribute(gemm_bf16<3>, cudaFuncAttributeMaxDynamicSharedMemorySize, (int)SMEM_G);
    cudaFuncSetAttribute(gemm_bf16<4>, cudaFuncAttributeMaxDynamicSharedMemorySize, (int)SMEM_G);

    // weight conversions + transposes
    f2bf_kernel<<<1024, 256>>>((const float4*)in_w,   (uint2*)w_in,   (2*kDI*kD)/4);
    f2bf_kernel<<<1024, 256>>>((const float4*)fuse_w, (uint2*)w_fuse, (kDI*kDI)/4);
    f2bf_kernel<<<512,  256>>>((const float4*)out_w,  (uint2*)w_out,  (kD*kDI)/4);
    transpose_f2bf<<<dim3(kDI/32, kD/32),  dim3(32,8)>>>(hb_w, hbT, kD,  kDI);
    transpose_f2bf<<<dim3(kDI/32, kDI/32), dim3(32,8)>>>(pw_w, pwT, kDI, kDI);

    // W2 = F2 @ hb_w : A = w_fuse[:,1024:] (lda 2048), B = hbT (ldb 1024)
    gemm_bf16<0><<<dim3(kDI/BN, kDI/BM), 256, SMEM_G>>>(
        w_fuse + kD, hbT, zero_b, kD, kDI, kD, W2, nullptr, nullptr, nullptr, nullptr, nullptr, kDI);

    // W3 = W2 @ pw_w : A = W2 (lda 2048), B = pwT (ldb 2048)
    gemm_bf16<0><<<dim3(kDI/BN, kDI/BM), 256, SMEM_G>>>(
        W2, pwT, zero_b, kDI, kDI, kDI, W3, nullptr, nullptr, nullptr, nullptr, nullptr, kDI);

    // folded bias
    zbias_kernel<<<(kDI*32)/256, 256>>>(fuse_b, ha_b, hb_b, pw_b, fuse_w, W2, zb);

    rmsnorm_kernel<<<kM, 256>>>(x, norm_w, hn);

    // in-proj: sigmoid(gate)/val split
    gemm_bf16<1><<<dim3((2*kDI)/BN, kM/BM), 256, SMEM_G>>>(
        hn, w_in, in_b, kD, kD, kD, gateB, valB, nullptr, nullptr, nullptr, nullptr, kDI);

    // fused depthwise convs
    dwconv_fused_kernel<<<(kM*kDI)/256, 256>>>(valB, dwa_k, dwa_b, sym_k, sym_b, a1, b1);

    // low-rank a-path
    lowrank_a2_kernel<<<(kM*32)/256, 256>>>(a1, Amat, a2);
    c1_kernel<<<(kDS*kD*32)/256, 256>>>(Bm, ha_w, C1);
    c2_kernel<<<(kDS*kDI*32)/256, 256>>>(C1, fuse_w, C2);
    aadd_kernel<<<(kM*kDI)/256, 256>>>(a2, C2, az);

    // fused b-path + a-path + gate:  y2 = gate * (b1 @ W3^T + az + zb)
    gemm_bf16<4><<<dim3(kDI/BN, kM/BM), 256, SMEM_G>>>(
        b1, W3, zb, kDI, kDI, kDI, y2, nullptr, gateB, az, nullptr, nullptr, kDI);

    // out-proj with residual add, fp32 out
    gemm_bf16<3><<<dim3(kD/BN, kM/BM), 256, SMEM_G>>>(
        y2, w_out, out_b, kDI, kDI, kDI, nullptr, nullptr, nullptr, nullptr, x, out, kD);
}